// round 1
// baseline (speedup 1.0000x reference)
#include <cuda_runtime.h>
#include <cstdint>

// ---------------------------------------------------------------------------
// kernel(i,j) = | prod_k cos((x_ik - y_jk)/2) |
// Identity: cos((a-b)/2) = cos(a/2)cos(b/2) + sin(a/2)sin(b/2)
// Stage 1: precompute (cos(v/2), sin(v/2)) for every element of x and y.
// Stage 2: FMA-only tiled outer product with f32x2 packed math.
// ---------------------------------------------------------------------------

#define D 16          // n_wires (fixed by problem)
#define TM 64         // tile rows (i)
#define TN 64         // tile cols (j)
#define THREADS 256   // 16x16 thread layout; each thread: 4 rows x 4 cols (2 f32x2 pairs)

// scratch: max 4096 rows per side
__device__ float2 g_csx[4096 * D];
__device__ float2 g_csy[4096 * D];

typedef unsigned long long u64;

__device__ __forceinline__ u64 pack2(float lo, float hi) {
    u64 r;
    asm("mov.b64 %0, {%1, %2};" : "=l"(r) : "r"(__float_as_uint(lo)), "r"(__float_as_uint(hi)));
    return r;
}
__device__ __forceinline__ void unpack2(u64 v, float& lo, float& hi) {
    unsigned a, b;
    asm("mov.b64 {%0, %1}, %2;" : "=r"(a), "=r"(b) : "l"(v));
    lo = __uint_as_float(a);
    hi = __uint_as_float(b);
}
__device__ __forceinline__ u64 mul2(u64 a, u64 b) {
    u64 r;
    asm("mul.rn.f32x2 %0, %1, %2;" : "=l"(r) : "l"(a), "l"(b));
    return r;
}
__device__ __forceinline__ u64 fma2(u64 a, u64 b, u64 c) {
    u64 r;
    asm("fma.rn.f32x2 %0, %1, %2, %3;" : "=l"(r) : "l"(a), "l"(b), "l"(c));
    return r;
}

// ---------------------------------------------------------------------------
// Stage 1: (cos, sin) of half-angles. Tiny (n*D + m*D = 64K elements).
// ---------------------------------------------------------------------------
__global__ void prep_kernel(const float* __restrict__ in, int total, int which) {
    int t = blockIdx.x * blockDim.x + threadIdx.x;
    if (t >= total) return;
    float s, c;
    sincosf(0.5f * in[t], &s, &c);
    float2* dst = which ? g_csy : g_csx;
    dst[t] = make_float2(c, s);
}

// ---------------------------------------------------------------------------
// Stage 2: tiled product kernel.
//   block tile: TM x TN, thread (tx,ty): rows ib=ty*4..+3, cols jb=tx*4..+3
//   acc[r][p] is f32x2 over cols (jb+2p, jb+2p+1)
// ---------------------------------------------------------------------------
__global__ __launch_bounds__(THREADS, 1)
void qk_kernel(float* __restrict__ out, int n, int m) {
    // x tiles: pre-duplicated packed (c,c)/(s,s), padded to 65 for conflict-free fill
    __shared__ __align__(16) u64 sxc[D][TM + 1];
    __shared__ __align__(16) u64 sxs[D][TM + 1];
    // y tiles: SoA floats, padded to 66 (keeps every row 8B-aligned, fill conflict-free)
    __shared__ __align__(16) float syc[D][TN + 2];
    __shared__ __align__(16) float sys[D][TN + 2];

    const int tid = threadIdx.x;
    const int i0 = blockIdx.y * TM;
    const int j0 = blockIdx.x * TN;

    // ---- fill shared (coalesced global reads: consecutive tid -> consecutive k) ----
    #pragma unroll
    for (int idx = tid; idx < TM * D; idx += THREADS) {
        int i = idx >> 4;       // 0..63
        int k = idx & (D - 1);  // 0..15
        float2 vx = g_csx[(i0 + i) * D + k];
        sxc[k][i] = pack2(vx.x, vx.x);
        sxs[k][i] = pack2(vx.y, vx.y);
        float2 vy = g_csy[(j0 + i) * D + k];
        syc[k][i] = vy.x;
        sys[k][i] = vy.y;
    }
    __syncthreads();

    const int tx = tid & 15;
    const int ty = tid >> 4;
    const int ib = ty * 4;
    const int jp = tx * 2;  // pair index base into y rows

    const u64 one2 = pack2(1.0f, 1.0f);
    u64 acc[4][2];
    #pragma unroll
    for (int r = 0; r < 4; ++r) {
        acc[r][0] = one2;
        acc[r][1] = one2;
    }

    #pragma unroll
    for (int k = 0; k < D; ++k) {
        const u64* ycr = reinterpret_cast<const u64*>(syc[k]);
        const u64* ysr = reinterpret_cast<const u64*>(sys[k]);
        u64 yc0 = ycr[jp];
        u64 yc1 = ycr[jp + 1];
        u64 ys0 = ysr[jp];
        u64 ys1 = ysr[jp + 1];
        #pragma unroll
        for (int r = 0; r < 4; ++r) {
            u64 xc = sxc[k][ib + r];
            u64 xs = sxs[k][ib + r];
            u64 t0 = fma2(xc, yc0, mul2(xs, ys0));
            u64 t1 = fma2(xc, yc1, mul2(xs, ys1));
            acc[r][0] = mul2(acc[r][0], t0);
            acc[r][1] = mul2(acc[r][1], t1);
        }
    }

    // ---- epilogue: |.| and contiguous float4 stores ----
    const int gj = j0 + tx * 4;
    #pragma unroll
    for (int r = 0; r < 4; ++r) {
        float a, b, c, d;
        unpack2(acc[r][0], a, b);
        unpack2(acc[r][1], c, d);
        float4 o = make_float4(fabsf(a), fabsf(b), fabsf(c), fabsf(d));
        *reinterpret_cast<float4*>(&out[(size_t)(i0 + ib + r) * m + gj]) = o;
    }
}

// ---------------------------------------------------------------------------
extern "C" void kernel_launch(void* const* d_in, const int* in_sizes, int n_in,
                              void* d_out, int out_size) {
    const float* x = (const float*)d_in[0];
    const float* y = (const float*)d_in[1];
    float* out = (float*)d_out;

    int nx = in_sizes[0];      // n * D
    int ny = in_sizes[1];      // m * D
    int n = nx / D;
    int m = ny / D;

    prep_kernel<<<(nx + 255) / 256, 256>>>(x, nx, 0);
    prep_kernel<<<(ny + 255) / 256, 256>>>(y, ny, 1);

    dim3 grid(m / TN, n / TM);
    qk_kernel<<<grid, THREADS>>>(out, n, m);
}

// round 2
// speedup vs baseline: 1.1345x; 1.1345x over previous
#include <cuda_runtime.h>
#include <cstdint>

// ---------------------------------------------------------------------------
// kernel(i,j) = | prod_k cos((x_ik - y_jk)/2) |
// Identity: cos((a-b)/2) = cos(a/2)cos(b/2) + sin(a/2)sin(b/2)
// Stage 1 (ONE launch): (cos, sin) of half-angles for both x and y -> scratch.
// Stage 2: FMA-only tiled outer product with f32x2 packed math.
// ---------------------------------------------------------------------------

#define D 16          // n_wires (fixed by problem)
#define TM 64         // tile rows (i)
#define TN 64         // tile cols (j)
#define THREADS 256   // 16x16 thread layout; each thread: 4 rows x 4 cols

// scratch: max 4096 rows per side
__device__ float2 g_csx[4096 * D];
__device__ float2 g_csy[4096 * D];

typedef unsigned long long u64;

__device__ __forceinline__ u64 pack2(float lo, float hi) {
    u64 r;
    asm("mov.b64 %0, {%1, %2};" : "=l"(r) : "r"(__float_as_uint(lo)), "r"(__float_as_uint(hi)));
    return r;
}
__device__ __forceinline__ void unpack2(u64 v, float& lo, float& hi) {
    unsigned a, b;
    asm("mov.b64 {%0, %1}, %2;" : "=r"(a), "=r"(b) : "l"(v));
    lo = __uint_as_float(a);
    hi = __uint_as_float(b);
}
__device__ __forceinline__ u64 mul2(u64 a, u64 b) {
    u64 r;
    asm("mul.rn.f32x2 %0, %1, %2;" : "=l"(r) : "l"(a), "l"(b));
    return r;
}
__device__ __forceinline__ u64 fma2(u64 a, u64 b, u64 c) {
    u64 r;
    asm("fma.rn.f32x2 %0, %1, %2, %3;" : "=l"(r) : "l"(a), "l"(b), "l"(c));
    return r;
}

// ---------------------------------------------------------------------------
// Stage 1: fused — one launch covers x then y. Exact sincosf (rel-err safety
// near cos zero-crossings; libdevice keeps ~ulp RELATIVE error there).
// ---------------------------------------------------------------------------
__global__ void prep_both(const float* __restrict__ x, const float* __restrict__ y,
                          int nx, int ny) {
    int t = blockIdx.x * blockDim.x + threadIdx.x;
    if (t < nx) {
        float s, c;
        sincosf(0.5f * x[t], &s, &c);
        g_csx[t] = make_float2(c, s);
    } else if (t < nx + ny) {
        int u = t - nx;
        float s, c;
        sincosf(0.5f * y[u], &s, &c);
        g_csy[u] = make_float2(c, s);
    }
}

// ---------------------------------------------------------------------------
// Stage 2: tiled product kernel.
//   block tile: TM x TN, thread (tx,ty): rows ib=ty*4..+3, cols jb=tx*4..+3
//   acc[r][p] is f32x2 over cols (jb+2p, jb+2p+1)
// x in shared as interleaved 16B records: sx[k][2i]=(c,c) sx[k][2i+1]=(s,s)
//   -> one LDS.128 per (k, row).
// y rows padded to 68 floats (272B = 17*16) so pair loads are aligned LDS.128.
// ---------------------------------------------------------------------------
#define XPITCH (2 * TM + 2)   // u64s per k-row: 130 -> 1040B = 65*16, 16B-aligned rows
#define YPITCH (TN + 4)       // floats per k-row: 68 -> 272B = 17*16, 16B-aligned rows

__global__ __launch_bounds__(THREADS)
void qk_kernel(float* __restrict__ out, int n, int m) {
    __shared__ __align__(16) u64 sx[D][XPITCH];
    __shared__ __align__(16) float syc[D][YPITCH];
    __shared__ __align__(16) float sys[D][YPITCH];

    const int tid = threadIdx.x;
    const int i0 = blockIdx.y * TM;
    const int j0 = blockIdx.x * TN;

    // ---- fill shared (coalesced global reads: consecutive tid -> consecutive k) ----
    #pragma unroll
    for (int idx = tid; idx < TM * D; idx += THREADS) {
        int i = idx >> 4;       // 0..63
        int k = idx & (D - 1);  // 0..15
        float2 vx = g_csx[(i0 + i) * D + k];
        sx[k][2 * i]     = pack2(vx.x, vx.x);
        sx[k][2 * i + 1] = pack2(vx.y, vx.y);
        float2 vy = g_csy[(j0 + i) * D + k];
        syc[k][i] = vy.x;
        sys[k][i] = vy.y;
    }
    __syncthreads();

    const int tx = tid & 15;
    const int ty = tid >> 4;
    const int ib = ty * 4;
    const int jp = tx * 2;  // u64-pair index base into y rows

    const u64 one2 = pack2(1.0f, 1.0f);
    u64 acc[4][2];
    #pragma unroll
    for (int r = 0; r < 4; ++r) {
        acc[r][0] = one2;
        acc[r][1] = one2;
    }

    #pragma unroll
    for (int k = 0; k < D; ++k) {
        // y: two aligned LDS.128 (4 floats each) covering cols jb..jb+3
        const ulonglong2* ycr = reinterpret_cast<const ulonglong2*>(syc[k]);
        const ulonglong2* ysr = reinterpret_cast<const ulonglong2*>(sys[k]);
        ulonglong2 yc = ycr[tx];
        ulonglong2 ys = ysr[tx];
        const ulonglong2* xr = reinterpret_cast<const ulonglong2*>(sx[k]);
        #pragma unroll
        for (int r = 0; r < 4; ++r) {
            ulonglong2 xv = xr[ib + r];       // one LDS.128: (cc, ss)
            u64 t0 = fma2(xv.x, yc.x, mul2(xv.y, ys.x));
            u64 t1 = fma2(xv.x, yc.y, mul2(xv.y, ys.y));
            acc[r][0] = mul2(acc[r][0], t0);
            acc[r][1] = mul2(acc[r][1], t1);
        }
    }

    // ---- epilogue: |.| and contiguous float4 stores ----
    const int gj = j0 + tx * 4;
    #pragma unroll
    for (int r = 0; r < 4; ++r) {
        float a, b, c, d;
        unpack2(acc[r][0], a, b);
        unpack2(acc[r][1], c, d);
        float4 o = make_float4(fabsf(a), fabsf(b), fabsf(c), fabsf(d));
        *reinterpret_cast<float4*>(&out[(size_t)(i0 + ib + r) * m + gj]) = o;
    }
}

// ---------------------------------------------------------------------------
extern "C" void kernel_launch(void* const* d_in, const int* in_sizes, int n_in,
                              void* d_out, int out_size) {
    const float* x = (const float*)d_in[0];
    const float* y = (const float*)d_in[1];
    float* out = (float*)d_out;

    int nx = in_sizes[0];      // n * D
    int ny = in_sizes[1];      // m * D
    int n = nx / D;
    int m = ny / D;

    int total = nx + ny;
    prep_both<<<(total + 255) / 256, 256>>>(x, y, nx, ny);

    dim3 grid(m / TN, n / TM);
    qk_kernel<<<grid, THREADS>>>(out, n, m);
}

// round 3
// speedup vs baseline: 1.2909x; 1.1379x over previous
#include <cuda_runtime.h>
#include <cstdint>

// ---------------------------------------------------------------------------
// kernel(i,j) = | prod_k cos((x_ik - y_jk)/2) |
//   cos((a-b)/2) = cos(a/2)cos(b/2) + sin(a/2)sin(b/2)
//                = cos(a/2)cos(b/2) * (1 + tan(a/2)tan(b/2))
// => out[i][j] = | Px_i * Py_j * prod_k (1 + tx_ik * ty_jk) |
// Stage 1 (one launch): tan tables + row/col cos-products (warp shuffle).
// Stage 2: FMA-only tiled kernel, 2 packed ops per 2 outputs per k.
// ---------------------------------------------------------------------------

#define D 16          // n_wires (fixed)
#define TM 128        // tile rows (i)
#define TN 128        // tile cols (j)
#define THREADS 256   // 16x16 threads; each thread computes 8x8 outputs

__device__ float g_tx[4096 * D];
__device__ float g_ty[4096 * D];
__device__ float g_px[4096];
__device__ float g_py[4096];

typedef unsigned long long u64;

__device__ __forceinline__ u64 pack2(float lo, float hi) {
    u64 r;
    asm("mov.b64 %0, {%1, %2};" : "=l"(r) : "r"(__float_as_uint(lo)), "r"(__float_as_uint(hi)));
    return r;
}
__device__ __forceinline__ void unpack2(u64 v, float& lo, float& hi) {
    unsigned a, b;
    asm("mov.b64 {%0, %1}, %2;" : "=r"(a), "=r"(b) : "l"(v));
    lo = __uint_as_float(a);
    hi = __uint_as_float(b);
}
__device__ __forceinline__ u64 mul2(u64 a, u64 b) {
    u64 r;
    asm("mul.rn.f32x2 %0, %1, %2;" : "=l"(r) : "l"(a), "l"(b));
    return r;
}
__device__ __forceinline__ u64 fma2(u64 a, u64 b, u64 c) {
    u64 r;
    asm("fma.rn.f32x2 %0, %1, %2, %3;" : "=l"(r) : "l"(a), "l"(b), "l"(c));
    return r;
}

// ---------------------------------------------------------------------------
// Stage 1: one element per thread; warp-shuffle product over each 16-lane
// half gives the per-row cos-product. Exact sincosf; c clamped consistently
// (same clamped c feeds both tan and the product => reconstruction exact).
// ---------------------------------------------------------------------------
__global__ void prep_kernel(const float* __restrict__ x, const float* __restrict__ y,
                            int nx, int ny) {
    int t = blockIdx.x * blockDim.x + threadIdx.x;
    int total = nx + ny;
    bool live = t < total;
    bool inx = t < nx;
    int u = inx ? t : t - nx;
    float v = 0.0f;
    if (live) v = inx ? x[t] : y[u];
    float s, c;
    sincosf(0.5f * v, &s, &c);
    if (fabsf(c) < 1e-20f) c = copysignf(1e-20f, c);
    float tn = s / c;
    float p = c;
    p *= __shfl_xor_sync(0xffffffffu, p, 1);
    p *= __shfl_xor_sync(0xffffffffu, p, 2);
    p *= __shfl_xor_sync(0xffffffffu, p, 4);
    p *= __shfl_xor_sync(0xffffffffu, p, 8);
    if (live) {
        if (inx) g_tx[u] = tn; else g_ty[u] = tn;
        if ((u & (D - 1)) == 0) {
            int row = u >> 4;
            if (inx) g_px[row] = p; else g_py[row] = p;
        }
    }
}

// ---------------------------------------------------------------------------
// Stage 2: 128x128 tile, 256 threads, thread (tx,ty) -> rows ty*8.., cols tx*8..
// x tans duplicated (t,t) in smem (LDS.64 broadcast in main loop);
// y tans scalar, pair-loaded as LDS.128.
// ---------------------------------------------------------------------------
__global__ __launch_bounds__(THREADS, 2)
void qk_kernel(float* __restrict__ out, int n, int m) {
    __shared__ __align__(16) u64 sxt[D][TM + 2];     // (t,t) duplicated
    __shared__ __align__(16) float syt[D][TN + 4];   // pitch 132 floats (16B mult)
    __shared__ __align__(16) u64 spx[TM];            // (px,px) duplicated
    __shared__ __align__(16) float spy[TN];

    const int tid = threadIdx.x;
    const int i0 = blockIdx.y * TM;
    const int j0 = blockIdx.x * TN;

    // ---- fill (coalesced global reads) ----
    #pragma unroll
    for (int idx = tid; idx < TM * D; idx += THREADS) {
        int i = idx >> 4;
        int k = idx & (D - 1);
        float vx = g_tx[(i0 + i) * D + k];
        sxt[k][i] = pack2(vx, vx);
        syt[k][i] = g_ty[(j0 + i) * D + k];
    }
    if (tid < TM) {
        float p = g_px[i0 + tid];
        spx[tid] = pack2(p, p);
    } else {
        spy[tid - TM] = g_py[j0 + tid - TM];
    }
    __syncthreads();

    const int tx = tid & 15;
    const int ty = tid >> 4;
    const int ib = ty * 8;
    const int jb = tx * 8;

    const u64 one2 = pack2(1.0f, 1.0f);
    u64 acc[8][4];
    #pragma unroll
    for (int r = 0; r < 8; ++r)
        #pragma unroll
        for (int p = 0; p < 4; ++p)
            acc[r][p] = one2;

    #pragma unroll
    for (int k = 0; k < D; ++k) {
        // y: two aligned LDS.128 covering 8 cols (4 f32x2 pairs)
        ulonglong2 ya = *reinterpret_cast<const ulonglong2*>(&syt[k][jb]);
        ulonglong2 yb = *reinterpret_cast<const ulonglong2*>(&syt[k][jb + 4]);
        #pragma unroll
        for (int r = 0; r < 8; ++r) {
            u64 xt = sxt[k][ib + r];   // LDS.64, broadcast across 16 lanes
            acc[r][0] = fma2(acc[r][0], mul2(xt, ya.x), acc[r][0]);
            acc[r][1] = fma2(acc[r][1], mul2(xt, ya.y), acc[r][1]);
            acc[r][2] = fma2(acc[r][2], mul2(xt, yb.x), acc[r][2]);
            acc[r][3] = fma2(acc[r][3], mul2(xt, yb.y), acc[r][3]);
        }
    }

    // ---- epilogue: scale by Px*Py, abs, contiguous float4 stores ----
    ulonglong2 pya = *reinterpret_cast<const ulonglong2*>(&spy[jb]);
    ulonglong2 pyb = *reinterpret_cast<const ulonglong2*>(&spy[jb + 4]);
    const int gj = j0 + jb;
    #pragma unroll
    for (int r = 0; r < 8; ++r) {
        u64 px2 = spx[ib + r];
        u64 v0 = mul2(mul2(acc[r][0], px2), pya.x);
        u64 v1 = mul2(mul2(acc[r][1], px2), pya.y);
        u64 v2 = mul2(mul2(acc[r][2], px2), pyb.x);
        u64 v3 = mul2(mul2(acc[r][3], px2), pyb.y);
        float a0, a1, b0, b1, c0, c1, d0, d1;
        unpack2(v0, a0, a1);
        unpack2(v1, b0, b1);
        unpack2(v2, c0, c1);
        unpack2(v3, d0, d1);
        float* row = &out[(size_t)(i0 + ib + r) * m + gj];
        *reinterpret_cast<float4*>(row) =
            make_float4(fabsf(a0), fabsf(a1), fabsf(b0), fabsf(b1));
        *reinterpret_cast<float4*>(row + 4) =
            make_float4(fabsf(c0), fabsf(c1), fabsf(d0), fabsf(d1));
    }
}

// ---------------------------------------------------------------------------
extern "C" void kernel_launch(void* const* d_in, const int* in_sizes, int n_in,
                              void* d_out, int out_size) {
    const float* x = (const float*)d_in[0];
    const float* y = (const float*)d_in[1];
    float* out = (float*)d_out;

    int nx = in_sizes[0];      // n * D
    int ny = in_sizes[1];      // m * D
    int n = nx / D;
    int m = ny / D;

    int total = nx + ny;
    prep_kernel<<<(total + 255) / 256, 256>>>(x, y, nx, ny);

    dim3 grid(m / TN, n / TM);
    qk_kernel<<<grid, THREADS>>>(out, n, m);
}